// round 2
// baseline (speedup 1.0000x reference)
#include <cuda_runtime.h>
#include <math.h>

#define BB    1024
#define TT    64
#define FF    18
#define UU    128
#define GATE3 (3 * UU)   // 384

// One CTA per batch row, 128 threads (one per hidden unit u).
// Per-row state cache in shared memory models table[:, b] exactly:
// at most TT distinct ids can ever be written in a row.
__global__ __launch_bounds__(128)
void feedzai_rnn_kernel(const float* __restrict__ inputs,      // [B, T, F]
                        const float* __restrict__ sync_states, // [NIDS, B, U]
                        const float* __restrict__ wk,          // [F, 3U]
                        const float* __restrict__ rk,          // [U, 3U]
                        const float* __restrict__ bias,        // [3U]
                        const float* __restrict__ dw,          // [U, 64]
                        const float* __restrict__ db,          // [64]
                        const float* __restrict__ ow,          // [64, 1]
                        const float* __restrict__ ob,          // [1]
                        float* __restrict__ out)               // [B, 1]
{
    __shared__ float x_row[TT * FF];        // this row's inputs (4608 B)
    __shared__ int   ids_cache[TT];
    __shared__ float h_cache[TT][UU];       // 32 KB
    __shared__ float h_sh[UU];              // h broadcast for hz dot
    __shared__ float red[64];

    const int b = blockIdx.x;
    const int u = threadIdx.x;              // 0..127

    // Stage this row's input sequence into smem (contiguous 4.6 KB).
    for (int i = u; i < TT * FF; i += 128)
        x_row[i] = inputs[(size_t)b * TT * FF + i];

    // Per-thread input-to-hidden weights live in registers (54 floats).
    float wz[FF], wr[FF], wh[FF];
#pragma unroll
    for (int k = 0; k < FF; k++) {
        wz[k] = wk[k * GATE3 + u];
        wr[k] = wk[k * GATE3 + UU + u];
        wh[k] = wk[k * GATE3 + 2 * UU + u];
    }
    const float bz = bias[u], br = bias[UU + u], bh = bias[2 * UU + u];
    __syncthreads();

    int   count  = 0;       // identical across all threads
    float h_last = 0.0f;

    for (int t = 0; t < TT; t++) {
        // id is stored as an exact integer-valued float in feature column 0.
        const int id = (int)x_row[t * FF];

        // All threads redundantly scan the cache (broadcast smem reads).
        int slot = -1;
        for (int s = 0; s < count; s++)
            if (ids_cache[s] == id) slot = s;

        // Gather h: from cache if this id was written earlier in this row,
        // otherwise from the initial sync_states table (correct for any input).
        float h_u;
        if (slot >= 0) h_u = h_cache[slot][u];
        else           h_u = sync_states[((size_t)id * BB + b) * UU + u];
        h_sh[u] = h_u;

        // Full-block OR barrier: also publishes h_sh.
        const int any_h = __syncthreads_or(h_u != 0.0f);

        // xz = x_t @ kernel + bias  (weights in registers, x broadcast)
        float az = bz, ar = br, ah = bh;
#pragma unroll
        for (int k = 0; k < FF; k++) {
            const float x = x_row[t * FF + k];
            az = fmaf(x, wz[k], az);
            ar = fmaf(x, wr[k], ar);
            ah = fmaf(x, wh[k], ah);
        }

        // hz = h @ rec_kernel — only when h is not identically zero (~3% of steps).
        float gz = 0.0f, gr = 0.0f, gh = 0.0f;
        if (any_h) {
#pragma unroll 4
            for (int k = 0; k < UU; k++) {
                const float hv = h_sh[k];
                const float* r = rk + k * GATE3;
                gz = fmaf(hv, r[u],          gz);
                gr = fmaf(hv, r[UU + u],     gr);
                gh = fmaf(hv, r[2 * UU + u], gh);
            }
        }

        // Gates (keras hard_sigmoid) + candidate.
        const float z  = fminf(fmaxf(0.2f * (az + gz) + 0.5f, 0.0f), 1.0f);
        const float rr = fminf(fmaxf(0.2f * (ar + gr) + 0.5f, 0.0f), 1.0f);
        const float cand = tanhf(ah + rr * gh);
        const float hn = z * h_u + (1.0f - z) * cand;

        // Scatter h_new back into the cache (insert or overwrite).
        const int wslot = (slot >= 0) ? slot : count;
        h_cache[wslot][u] = hn;
        if (slot < 0) {
            if (u == 0) ids_cache[count] = id;
            count++;
        }
        h_last = hn;
        __syncthreads();   // ids_cache + h_cache visible before next step's scan
    }

    // Dense head: relu(h_last @ dense_w + db) @ out_w + ob -> sigmoid
    h_sh[u] = h_last;
    __syncthreads();
    if (u < 64) {
        float acc = db[u];
#pragma unroll 4
        for (int k = 0; k < UU; k++)
            acc = fmaf(h_sh[k], dw[k * 64 + u], acc);
        acc = fmaxf(acc, 0.0f);
        red[u] = acc * ow[u];
    }
    __syncthreads();
    if (u == 0) {
        float s = ob[0];
#pragma unroll
        for (int j = 0; j < 64; j++) s += red[j];
        out[b] = 1.0f / (1.0f + expf(-s));
    }
}

extern "C" void kernel_launch(void* const* d_in, const int* in_sizes, int n_in,
                              void* d_out, int out_size)
{
    const float* inputs      = (const float*)d_in[0];
    const float* sync_states = (const float*)d_in[1];
    const float* wk          = (const float*)d_in[2];
    const float* rk          = (const float*)d_in[3];
    const float* bias        = (const float*)d_in[4];
    const float* dw          = (const float*)d_in[5];
    const float* db          = (const float*)d_in[6];
    const float* ow          = (const float*)d_in[7];
    const float* ob          = (const float*)d_in[8];
    float* out = (float*)d_out;

    feedzai_rnn_kernel<<<BB, 128>>>(inputs, sync_states, wk, rk, bias,
                                    dw, db, ow, ob, out);
}

// round 3
// speedup vs baseline: 1.2628x; 1.2628x over previous
#include <cuda_runtime.h>
#include <math.h>

#define BB    1024
#define TT    64
#define FF    18
#define XP    20          // padded x row (16B-aligned float4 loads)
#define UU    128
#define G3    (3 * UU)    // 384

// One CTA per batch row, 128 threads (one per hidden unit u).
// Phase 1: stage x, precompute slot map (first-occurrence index per step)
//          and per-step "needs recurrence" flags.
// Phase 2: bulk-prefetch all first-occurrence sync_states rows (high MLP).
// Phase 3: barrier-free recurrence loop (barriers only on rare nonzero-h steps).
__global__ __launch_bounds__(128)
void feedzai_rnn_kernel(const float* __restrict__ inputs,      // [B, T, F]
                        const float* __restrict__ sync_states, // [NIDS, B, U]
                        const float* __restrict__ wk,          // [F, 3U]
                        const float* __restrict__ rk,          // [U, 3U]
                        const float* __restrict__ bias,        // [3U]
                        const float* __restrict__ dw,          // [U, 64]
                        const float* __restrict__ db,          // [64]
                        const float* __restrict__ ow,          // [64, 1]
                        const float* __restrict__ ob,          // [1]
                        float* __restrict__ out)               // [B, 1]
{
    __shared__ float x_row[TT * XP];        // 5120 B
    __shared__ int   slot_sh[TT];           // low16 = slot, bit16 = need-recurrence
    __shared__ float h_cache[TT][UU];       // 32768 B
    __shared__ float h_sh[UU];              // 512 B     (total 38656 B)

    const int b = blockIdx.x;
    const int u = threadIdx.x;              // 0..127

    // ---- stage this row's inputs into padded smem ----
    for (int i = u; i < TT * FF; i += 128) {
        const int t = i / FF, k = i - t * FF;
        x_row[t * XP + k] = inputs[(size_t)b * TT * FF + i];
    }

    // ---- input-to-hidden weights live in registers (54 floats/thread) ----
    float wz[FF], wr[FF], wh[FF];
#pragma unroll
    for (int k = 0; k < FF; k++) {
        wz[k] = wk[k * G3 + u];
        wr[k] = wk[k * G3 + UU + u];
        wh[k] = wk[k * G3 + 2 * UU + u];
    }
    const float bz = bias[u], br = bias[UU + u], bh = bias[2 * UU + u];
    __syncthreads();

    // ---- slot precompute: thread t finds first occurrence of its step's id ----
    if (u < TT) {
        const int myid = (int)x_row[u * XP];
        int s = 0;
        while ((int)x_row[s * XP] != myid) s++;         // s <= u always terminates
        slot_sh[u] = s | ((s != u) ? (1 << 16) : 0);    // repeat => recurrence needed
    }
    __syncthreads();

    // ---- bulk prefetch: load every first-occurrence state row, flag nonzero ----
#pragma unroll 4
    for (int t = 0; t < TT; t++) {
        if ((slot_sh[t] & 0xFFFF) == t) {               // first occurrence of this id
            const int id = (int)x_row[t * XP];
            const float v = __ldcs(&sync_states[((size_t)id * BB + b) * UU + u]);
            h_cache[t][u] = v;
            if (v != 0.0f) atomicOr(&slot_sh[t], 1 << 16);  // predicated: 0 atomics when states are zero
        }
    }
    __syncthreads();

    // ---- main recurrence: no barriers in the common (zero-h) path ----
    float h_last = 0.0f;
#pragma unroll 1
    for (int t = 0; t < TT; t++) {
        const int   sr   = slot_sh[t];
        const int   slot = sr & 0xFFFF;
        const float h_u  = h_cache[slot][u];            // own lane only

        const float4 x0 = *(const float4*)(x_row + t * XP);
        const float4 x1 = *(const float4*)(x_row + t * XP + 4);
        const float4 x2 = *(const float4*)(x_row + t * XP + 8);
        const float4 x3 = *(const float4*)(x_row + t * XP + 12);
        const float2 x4 = *(const float2*)(x_row + t * XP + 16);
        const float xv[FF] = { x0.x, x0.y, x0.z, x0.w,  x1.x, x1.y, x1.z, x1.w,
                               x2.x, x2.y, x2.z, x2.w,  x3.x, x3.y, x3.z, x3.w,
                               x4.x, x4.y };

        float az = bz, ar = br, ah = bh;
#pragma unroll
        for (int k = 0; k < FF; k++) {
            az = fmaf(xv[k], wz[k], az);
            ar = fmaf(xv[k], wr[k], ar);
            ah = fmaf(xv[k], wh[k], ah);
        }

        float gz = 0.0f, gr = 0.0f, gh = 0.0f;
        if (sr >> 16) {                                 // rare: h not identically zero
            h_sh[u] = h_u;
            __syncthreads();
#pragma unroll 4
            for (int k = 0; k < UU; k++) {
                const float hv = h_sh[k];
                const float* r = rk + k * G3;
                gz = fmaf(hv, __ldg(r + u),          gz);
                gr = fmaf(hv, __ldg(r + UU + u),     gr);
                gh = fmaf(hv, __ldg(r + 2 * UU + u), gh);
            }
            __syncthreads();                            // protect h_sh reuse
        }

        const float zz  = __saturatef(0.2f * (az + gz) + 0.5f);
        const float rr  = __saturatef(0.2f * (ar + gr) + 0.5f);
        const float pre = ah + rr * gh;
        const float e   = __expf(2.0f * pre);           // tanh(pre) = 1 - 2/(e+1)
        const float hh  = 1.0f - __fdividef(2.0f, e + 1.0f);
        const float hn  = zz * h_u + (1.0f - zz) * hh;

        h_cache[slot][u] = hn;                          // own lane only
        h_last = hn;
    }

    // ---- dense head: relu(h @ dw + db) @ ow + ob -> sigmoid ----
    h_sh[u] = h_last;
    __syncthreads();
    float* red = (float*)slot_sh;                       // reuse smem
    if (u < 64) {
        float acc = db[u];
#pragma unroll 4
        for (int k = 0; k < UU; k++)
            acc = fmaf(h_sh[k], dw[k * 64 + u], acc);
        acc = fmaxf(acc, 0.0f) * ow[u];
#pragma unroll
        for (int o = 16; o; o >>= 1)
            acc += __shfl_down_sync(0xffffffff, acc, o);
        if ((u & 31) == 0) red[u >> 5] = acc;
    }
    __syncthreads();
    if (u == 0) {
        const float s = ob[0] + red[0] + red[1];
        out[b] = __fdividef(1.0f, 1.0f + __expf(-s));
    }
}

extern "C" void kernel_launch(void* const* d_in, const int* in_sizes, int n_in,
                              void* d_out, int out_size)
{
    const float* inputs      = (const float*)d_in[0];
    const float* sync_states = (const float*)d_in[1];
    const float* wk          = (const float*)d_in[2];
    const float* rk          = (const float*)d_in[3];
    const float* bias        = (const float*)d_in[4];
    const float* dw          = (const float*)d_in[5];
    const float* db          = (const float*)d_in[6];
    const float* ow          = (const float*)d_in[7];
    const float* ob          = (const float*)d_in[8];
    float* out = (float*)d_out;

    feedzai_rnn_kernel<<<BB, 128>>>(inputs, sync_states, wk, rk, bias,
                                    dw, db, ow, ob, out);
}